// round 15
// baseline (speedup 1.0000x reference)
#include <cuda_runtime.h>
#include <cuda_fp16.h>
#include <cstdint>

// Problem constants
#define SLEN   2048
#define BSZ    8
#define IN_DIM 1024
#define NH     16
#define DH     64
#define NROWS  (SLEN*BSZ)              // 16384
#define NOUT   (NH*(3*DH+1))           // 3088
#define HPAD   194                     // padded head stride
#define NOUT2  (NH*HPAD)               // 3104
#define NOUT_PAD 3200

// ---------------- device scratch ----------------
__device__ __half g_h[(size_t)NROWS * IN_DIM];
__device__ __half g_qkvb[(size_t)NROWS * NOUT2];
__device__ float g_q[(size_t)BSZ*NH*SLEN*DH];
__device__ float g_k[(size_t)BSZ*NH*SLEN*DH];
__device__ float g_v[(size_t)BSZ*NH*SLEN*DH];
__device__ float g_beta[(size_t)BSZ*NH*SLEN];
__device__ __half g_o[(size_t)NROWS * IN_DIM];
__device__ __half g_ws_t[(size_t)NOUT_PAD * IN_DIM];
__device__ __half g_wo_t[(size_t)IN_DIM * IN_DIM];

// ---------------- helpers ----------------
__device__ __forceinline__ void cp_async16(void* smem_dst, const void* gsrc) {
    unsigned s = (unsigned)__cvta_generic_to_shared(smem_dst);
    asm volatile("cp.async.cg.shared.global [%0], [%1], 16;\n" :: "r"(s), "l"(gsrc));
}
__device__ __forceinline__ float elu_p1(float x) {
    return x > 0.f ? x + 1.f : __expf(x);
}
__device__ __forceinline__ void mma_f16(float* d, const uint32_t* a, const uint32_t* b) {
    asm volatile("mma.sync.aligned.m16n8k16.row.col.f32.f16.f16.f32 "
        "{%0,%1,%2,%3}, {%4,%5,%6,%7}, {%8,%9}, {%0,%1,%2,%3};"
        : "+f"(d[0]), "+f"(d[1]), "+f"(d[2]), "+f"(d[3])
        : "r"(a[0]), "r"(a[1]), "r"(a[2]), "r"(a[3]), "r"(b[0]), "r"(b[1]));
}
__device__ __forceinline__ void ldsm_x4(uint32_t* r, uint32_t saddr) {
    asm volatile("ldmatrix.sync.aligned.m8n8.x4.shared.b16 {%0,%1,%2,%3}, [%4];"
        : "=r"(r[0]), "=r"(r[1]), "=r"(r[2]), "=r"(r[3]) : "r"(saddr));
}
__device__ __forceinline__ void ldsm_x2(uint32_t* r, uint32_t saddr) {
    asm volatile("ldmatrix.sync.aligned.m8n8.x2.shared.b16 {%0,%1}, [%2];"
        : "=r"(r[0]), "=r"(r[1]) : "r"(saddr));
}

// ---------------- cast+transpose weights: W[K][N] f32 -> T[n'][K] f16 ----------------
__global__ __launch_bounds__(256) void cast_transpose_f16(
    const float* __restrict__ W, __half* __restrict__ T, int K, int N, int pad)
{
    __shared__ float tile[32][33];
    int n0 = blockIdx.x * 32, k0 = blockIdx.y * 32;
    int tx = threadIdx.x, ty = threadIdx.y;
    #pragma unroll
    for (int i = 0; i < 32; i += 8) {
        int k = k0 + ty + i, n = n0 + tx;
        tile[ty + i][tx] = (n < N) ? W[(size_t)k * N + n] : 0.f;
    }
    __syncthreads();
    #pragma unroll
    for (int i = 0; i < 32; i += 8) {
        int n = n0 + ty + i, k = k0 + tx;
        if (n < N) {
            int np = pad ? (n + n / 193) : n;
            T[(size_t)np * K + k] = __float2half(tile[tx][ty + i]);
        }
    }
}

// ---------------- LayerNorm ----------------
__global__ __launch_bounds__(256) void ln_kernel(
    const float* __restrict__ x, const float* __restrict__ w,
    const float* __restrict__ b, __half* __restrict__ hout)
{
    int row = blockIdx.x;
    int t = threadIdx.x;
    const float4* xr = (const float4*)(x + (size_t)row * IN_DIM);
    float4 v = xr[t];
    float s  = v.x + v.y + v.z + v.w;
    float ss = v.x*v.x + v.y*v.y + v.z*v.z + v.w*v.w;
    #pragma unroll
    for (int o = 16; o; o >>= 1) {
        s  += __shfl_xor_sync(0xffffffffu, s,  o);
        ss += __shfl_xor_sync(0xffffffffu, ss, o);
    }
    __shared__ float rs[8], rss[8];
    if ((t & 31) == 0) { rs[t >> 5] = s; rss[t >> 5] = ss; }
    __syncthreads();
    float S = 0.f, SS = 0.f;
    #pragma unroll
    for (int i = 0; i < 8; i++) { S += rs[i]; SS += rss[i]; }
    float mu = S * (1.f / IN_DIM);
    float var = SS * (1.f / IN_DIM) - mu * mu;
    float rstd = rsqrtf(var + 1e-5f);
    float4 wv = ((const float4*)w)[t];
    float4 bv = ((const float4*)b)[t];
    float o0 = (v.x - mu) * rstd * wv.x + bv.x;
    float o1 = (v.y - mu) * rstd * wv.y + bv.y;
    float o2 = (v.z - mu) * rstd * wv.z + bv.z;
    float o3 = (v.w - mu) * rstd * wv.w + bv.w;
    size_t base = (size_t)row * IN_DIM;
    ((__half2*)(hout + base))[2*t]   = __half2(__float2half(o0), __float2half(o1));
    ((__half2*)(hout + base))[2*t+1] = __half2(__float2half(o2), __float2half(o3));
}

// ---------------- f16 HGEMM (ldmatrix, 128B-row XOR-swizzle, 3-stage, KT=64) ----------------
#define KT  64
#define ARR_U32 (128 * 32)
#define STAGE_U32 (2 * ARR_U32)
#define GEMM_SMEM_BYTES (3 * STAGE_U32 * 4)

template<bool HOUT>
__global__ __launch_bounds__(256, 2) void gemm_f16(
    const __half* __restrict__ A, const __half* __restrict__ B,
    const float* __restrict__ Res, void* __restrict__ Cv,
    int N, int K)
{
    extern __shared__ __align__(16) uint32_t dsm[];

    const int tid  = threadIdx.x;
    const int warp = tid >> 5;
    const int lane = tid & 31;
    const int gid  = lane >> 2;
    const int tig  = lane & 3;
    const int wm   = warp & 1;
    const int wn   = warp >> 1;
    const int row0 = blockIdx.y * 128;
    const int col0 = blockIdx.x * 128;

    float acc[4][4][4];
    #pragma unroll
    for (int i = 0; i < 4; i++)
        #pragma unroll
        for (int j = 0; j < 4; j++)
            #pragma unroll
            for (int k = 0; k < 4; k++) acc[i][j][k] = 0.f;

    const int nk = K / KT;
    const uint32_t smem0 = (uint32_t)__cvta_generic_to_shared(dsm);

    auto load_stage = [&](int kt) {
        const int k0 = kt * KT;
        uint32_t* sb = dsm + (kt % 3) * STAGE_U32;
        #pragma unroll
        for (int it = 0; it < 4; it++) {
            int c = tid + it * 256;
            int r = c >> 3, f = c & 7;
            int fs = f ^ (r & 7);
            uint32_t* dst = sb + r * 32 + fs * 4;
            cp_async16(dst,           A + (size_t)(row0 + r) * K + k0 + f * 8);
            cp_async16(dst + ARR_U32, B + (size_t)(col0 + r) * K + k0 + f * 8);
        }
        asm volatile("cp.async.commit_group;\n" ::);
    };

    load_stage(0);
    load_stage(1);

    const int a_sub = lane >> 3;
    const int a_rin = lane & 7;
    const int a_row0 = wm * 64 + (a_sub & 1) * 8 + a_rin;
    const uint32_t a_byte0 = (uint32_t)(a_row0 * 128);
    uint32_t a_ch[4];
    #pragma unroll
    for (int kb = 0; kb < 4; kb++)
        a_ch[kb] = (uint32_t)((((kb * 2) + (a_sub >> 1)) ^ a_rin) * 16);
    const int b_row0 = wn * 32 + (lane & 7);
    const int b_sub = (lane >> 3) & 1;
    const uint32_t b_byte0 = (uint32_t)(b_row0 * 128);
    uint32_t b_ch[4];
    #pragma unroll
    for (int kb = 0; kb < 4; kb++)
        b_ch[kb] = (uint32_t)((((kb * 2) + b_sub) ^ (lane & 7)) * 16);

    for (int kt = 0; kt < nk; kt++) {
        asm volatile("cp.async.wait_group 1;\n" ::);
        __syncthreads();
        if (kt + 2 < nk) load_stage(kt + 2);
        else asm volatile("cp.async.commit_group;\n" ::);

        const uint32_t sbase = smem0 + (uint32_t)((kt % 3) * STAGE_U32 * 4);
        const uint32_t sA = sbase;
        const uint32_t sB = sbase + ARR_U32 * 4;

        #pragma unroll
        for (int kb = 0; kb < 4; kb++) {
            uint32_t af[4][4];
            #pragma unroll
            for (int mt = 0; mt < 4; mt++)
                ldsm_x4(af[mt], sA + a_byte0 + (uint32_t)(mt * 16 * 128) + a_ch[kb]);
            uint32_t bf[4][2];
            #pragma unroll
            for (int nt = 0; nt < 4; nt++)
                ldsm_x2(bf[nt], sB + b_byte0 + (uint32_t)(nt * 8 * 128) + b_ch[kb]);
            #pragma unroll
            for (int nt = 0; nt < 4; nt++)
                #pragma unroll
                for (int mt = 0; mt < 4; mt++) mma_f16(acc[mt][nt], af[mt], bf[nt]);
        }
    }

    #pragma unroll
    for (int mt = 0; mt < 4; mt++) {
        #pragma unroll
        for (int nt = 0; nt < 4; nt++) {
            int r = row0 + wm * 64 + mt * 16 + gid;
            int c = col0 + wn * 32 + nt * 8 + 2 * tig;
            if (c < N) {
                size_t o0 = (size_t)r * N + c;
                size_t o1 = (size_t)(r + 8) * N + c;
                if (HOUT) {
                    __half* C = (__half*)Cv;
                    *(__half2*)&C[o0] = __half2(__float2half(acc[mt][nt][0]),
                                                __float2half(acc[mt][nt][1]));
                    *(__half2*)&C[o1] = __half2(__float2half(acc[mt][nt][2]),
                                                __float2half(acc[mt][nt][3]));
                } else {
                    float* C = (float*)Cv;
                    float2 v0 = make_float2(acc[mt][nt][0], acc[mt][nt][1]);
                    float2 v1 = make_float2(acc[mt][nt][2], acc[mt][nt][3]);
                    if (Res) {
                        float2 r0 = *(const float2*)&Res[o0];
                        float2 r1 = *(const float2*)&Res[o1];
                        v0.x += r0.x; v0.y += r0.y;
                        v1.x += r1.x; v1.y += r1.y;
                    }
                    *(float2*)&C[o0] = v0;
                    *(float2*)&C[o1] = v1;
                }
            }
        }
    }
}

// ---------------- transform: f16 qkvb (padded heads) -> q,k,v,beta ----------------
__global__ __launch_bounds__(256) void transform_kernel(
    const __half* __restrict__ qkvb,
    float* __restrict__ Q, float* __restrict__ Kk,
    float* __restrict__ V, float* __restrict__ Beta)
{
    int gw   = blockIdx.x * 8 + (threadIdx.x >> 5);
    int lane = threadIdx.x & 31;
    int h  = gw & 15;
    int tb = gw >> 4;
    int b  = tb & 7;
    int t  = tb >> 3;
    const __half2* src2 = (const __half2*)(qkvb + (size_t)tb * NOUT2 + h * HPAD);
    size_t dst = ((size_t)(b * NH + h) * SLEN + t) * DH;

    float2 qf = __half22float2(src2[lane]);
    float q0 = elu_p1(qf.x), q1 = elu_p1(qf.y);
    float s = q0 + q1;
    #pragma unroll
    for (int o = 16; o; o >>= 1) s += __shfl_xor_sync(0xffffffffu, s, o);
    float inv = 1.f / s;
    *(float2*)&Q[dst + 2*lane] = make_float2(q0 * inv, q1 * inv);

    float2 kf = __half22float2(src2[32 + lane]);
    float k0 = elu_p1(kf.x), k1 = elu_p1(kf.y);
    s = k0 + k1;
    #pragma unroll
    for (int o = 16; o; o >>= 1) s += __shfl_xor_sync(0xffffffffu, s, o);
    inv = 1.f / s;
    *(float2*)&Kk[dst + 2*lane] = make_float2(k0 * inv, k1 * inv);

    float2 vf = __half22float2(src2[64 + lane]);
    *(float2*)&V[dst + 2*lane] = vf;

    if (lane == 0) {
        float x = __half2float(((const __half*)src2)[192]);
        Beta[(size_t)(b * NH + h) * SLEN + t] = 1.f / (1.f + __expf(-x));
    }
}

// ---------------- delta-rule scan v5: 1024 blocks x 2 warps, conflict-free smem ----------------
// Block = (head, row-octet). Warp wid owns rows wid*4..+3; lane: rloc=lane>>3 (4 rows),
// g=lane&7 (8 cols) -> W[8]/thread. Swizzle: logical 16B chunk c at physical (c>>1)+(c&1)*8
// -> lane g reads physical chunks {g, g+8}: all 32 banks distinct per LDS.128. 2-step blocked.
#define CH 16
__global__ __launch_bounds__(64) void scan_kernel(
    const float* __restrict__ Q, const float* __restrict__ Kk,
    const float* __restrict__ V, const float* __restrict__ Beta,
    __half* __restrict__ O)
{
    __shared__ __align__(16) float sk[2][CH][64];
    __shared__ __align__(16) float sq[2][CH][64];
    __shared__ __align__(16) float sv[2][CH][8];
    __shared__ __align__(16) float sb[2][CH];

    const int bh = blockIdx.x >> 3;       // 0..127
    const int w8 = (blockIdx.x & 7) * 8;  // octet base
    const int b = bh >> 4, h = bh & 15;
    const float* Kp = Kk   + (size_t)bh * SLEN * DH;
    const float* Vp = V    + (size_t)bh * SLEN * DH;
    const float* Qp = Q    + (size_t)bh * SLEN * DH;
    const float* Bp = Beta + (size_t)bh * SLEN;
    const int tid  = threadIdx.x;
    const int wid  = tid >> 5;
    const int lane = tid & 31;
    const int rloc = lane >> 3;           // 0..3
    const int g    = lane & 7;            // 0..7
    const int vrow = wid * 4 + rloc;      // 0..7

    float W[8];
    #pragma unroll
    for (int m = 0; m < 8; m++) W[m] = 0.f;

    auto issue = [&](int c) {
        int buf = c & 1;
        int t0 = c * CH;
        #pragma unroll
        for (int j = 0; j < 4; j++) {
            int idx = tid + j * 64;            // 0..255
            int tt = idx >> 4, f = idx & 15;
            int fp = (f >> 1) + (f & 1) * 8;   // swizzle
            cp_async16(&sk[buf][tt][fp * 4], Kp + (size_t)(t0 + tt) * DH + f * 4);
            cp_async16(&sq[buf][tt][fp * 4], Qp + (size_t)(t0 + tt) * DH + f * 4);
        }
        if (tid < 32) {
            int tt = tid >> 1, hf = tid & 1;
            cp_async16(&sv[buf][tt][hf * 4], Vp + (size_t)(t0 + tt) * DH + w8 + hf * 4);
        }
        if (tid >= 60) cp_async16(&sb[buf][(tid - 60) * 4], Bp + t0 + (tid - 60) * 4);
        asm volatile("cp.async.commit_group;\n" ::);
    };

    issue(0); issue(1);

    const int NC = SLEN / CH;
    const size_t obase = (size_t)b * IN_DIM + h * DH + w8 + vrow;

    for (int c = 0; c < NC; c++) {
        asm volatile("cp.async.wait_group 1;\n" ::);
        __syncthreads();
        const int buf = c & 1;

        #pragma unroll 2
        for (int p = 0; p < CH / 2; p++) {
            const int t1 = 2 * p, t2 = 2 * p + 1;
            // lane g's 8 values: physical chunk g (k[g*8..+3]) and g+8 (k[g*8+4..+7])
            float k1[8], k2[8], q1v[8], q2v[8];
            {
                float4 a = *(const float4*)&sk[buf][t1][g * 4];
                float4 a2 = *(const float4*)&sk[buf][t1][32 + g * 4];
                k1[0]=a.x; k1[1]=a.y; k1[2]=a.z; k1[3]=a.w;
                k1[4]=a2.x; k1[5]=a2.y; k1[6]=a2.z; k1[7]=a2.w;
                float4 bb = *(const float4*)&sk[buf][t2][g * 4];
                float4 b2 = *(const float4*)&sk[buf][t2][32 + g * 4];
                k2[0]=bb.x; k2[1]=bb.y; k2[2]=bb.z; k2[3]=bb.w;
                k2[4]=b2.x; k2[5]=b2.y; k2[6]=b2.z; k2[7]=b2.w;
                float4 cc = *(const float4*)&sq[buf][t1][g * 4];
                float4 c2 = *(const float4*)&sq[buf][t1][32 + g * 4];
                q1v[0]=cc.x; q1v[1]=cc.y; q1v[2]=cc.z; q1v[3]=cc.w;
                q1v[4]=c2.x; q1v[5]=c2.y; q1v[6]=c2.z; q1v[7]=c2.w;
                float4 dd = *(const float4*)&sq[buf][t2][g * 4];
                float4 d2 = *(const float4*)&sq[buf][t2][32 + g * 4];
                q2v[0]=dd.x; q2v[1]=dd.y; q2v[2]=dd.z; q2v[3]=dd.w;
                q2v[4]=d2.x; q2v[5]=d2.y; q2v[6]=d2.z; q2v[7]=d2.w;
            }
            float v1 = sv[buf][t1][vrow];
            float v2 = sv[buf][t2][vrow];
            float b1 = sb[buf][t1];
            float b2 = sb[buf][t2];

            // three dots off same W + kk, 2-acc each
            float pk1a = 0.f, pk1b = 0.f, pk2a = 0.f, pk2b = 0.f, kka = 0.f, kkb = 0.f;
            #pragma unroll
            for (int m = 0; m < 4; m++) {
                pk1a = fmaf(W[m],     k1[m],     pk1a);
                pk1b = fmaf(W[m + 4], k1[m + 4], pk1b);
                pk2a = fmaf(W[m],     k2[m],     pk2a);
                pk2b = fmaf(W[m + 4], k2[m + 4], pk2b);
                kka  = fmaf(k1[m],     k2[m],     kka);
                kkb  = fmaf(k1[m + 4], k2[m + 4], kkb);
            }
            float pk1 = pk1a + pk1b;
            float pk2 = pk2a + pk2b;
            float kk  = kka + kkb;
            pk1 += __shfl_xor_sync(0xffffffffu, pk1, 1);
            pk2 += __shfl_xor_sync(0xffffffffu, pk2, 1);
            kk  += __shfl_xor_sync(0xffffffffu, kk,  1);
            pk1 += __shfl_xor_sync(0xffffffffu, pk1, 2);
            pk2 += __shfl_xor_sync(0xffffffffu, pk2, 2);
            kk  += __shfl_xor_sync(0xffffffffu, kk,  2);
            pk1 += __shfl_xor_sync(0xffffffffu, pk1, 4);
            pk2 += __shfl_xor_sync(0xffffffffu, pk2, 4);
            kk  += __shfl_xor_sync(0xffffffffu, kk,  4);

            float d1 = b1 * (v1 - pk1);
            float d2 = b2 * (v2 - pk2 - d1 * kk);

            float po1a = 0.f, po1b = 0.f;
            #pragma unroll
            for (int m = 0; m < 4; m++) {
                W[m]     = fmaf(d1, k1[m],     W[m]);
                po1a     = fmaf(W[m],  q1v[m], po1a);
                W[m + 4] = fmaf(d1, k1[m + 4], W[m + 4]);
                po1b     = fmaf(W[m + 4], q1v[m + 4], po1b);
            }
            float po2a = 0.f, po2b = 0.f;
            #pragma unroll
            for (int m = 0; m < 4; m++) {
                W[m]     = fmaf(d2, k2[m],     W[m]);
                po2a     = fmaf(W[m],  q2v[m], po2a);
                W[m + 4] = fmaf(d2, k2[m + 4], W[m + 4]);
                po2b     = fmaf(W[m + 4], q2v[m + 4], po2b);
            }

            float po1 = po1a + po1b;
            float po2 = po2a + po2b;
            po1 += __shfl_xor_sync(0xffffffffu, po1, 1);
            po2 += __shfl_xor_sync(0xffffffffu, po2, 1);
            po1 += __shfl_xor_sync(0xffffffffu, po1, 2);
            po2 += __shfl_xor_sync(0xffffffffu, po2, 2);
            po1 += __shfl_xor_sync(0xffffffffu, po1, 4);
            po2 += __shfl_xor_sync(0xffffffffu, po2, 4);

            if (g == 0) {
                int tg1 = c * CH + t1;
                size_t off1 = (size_t)tg1 * (BSZ * IN_DIM) + obase;
                O[off1] = __float2half(po1);
                O[off1 + (BSZ * IN_DIM)] = __float2half(po2);
            }
        }
        __syncthreads();
        if (c + 2 < NC) issue(c + 2);
        else asm volatile("cp.async.commit_group;\n" ::);
    }
}

// ---------------- launcher ----------------
extern "C" void kernel_launch(void* const* d_in, const int* in_sizes, int n_in,
                              void* d_out, int out_size)
{
    const float* x      = (const float*)d_in[0];
    const float* ln_w   = (const float*)d_in[1];
    const float* ln_b   = (const float*)d_in[2];
    const float* w_slow = (const float*)d_in[3];
    const float* w_out  = (const float*)d_in[4];
    float* out = (float*)d_out;

    float *p_q, *p_k, *p_v, *p_beta;
    __half *p_h, *p_qkvb, *p_o, *p_ws, *p_wo;
    cudaGetSymbolAddress((void**)&p_qkvb, g_qkvb);
    cudaGetSymbolAddress((void**)&p_q,    g_q);
    cudaGetSymbolAddress((void**)&p_k,    g_k);
    cudaGetSymbolAddress((void**)&p_v,    g_v);
    cudaGetSymbolAddress((void**)&p_beta, g_beta);
    cudaGetSymbolAddress((void**)&p_h,    g_h);
    cudaGetSymbolAddress((void**)&p_o,    g_o);
    cudaGetSymbolAddress((void**)&p_ws,   g_ws_t);
    cudaGetSymbolAddress((void**)&p_wo,   g_wo_t);

    cudaFuncSetAttribute(gemm_f16<true>, cudaFuncAttributeMaxDynamicSharedMemorySize,
                         GEMM_SMEM_BYTES);
    cudaFuncSetAttribute(gemm_f16<false>, cudaFuncAttributeMaxDynamicSharedMemorySize,
                         GEMM_SMEM_BYTES);

    // 0. cast+transpose weights
    {
        dim3 blk(32, 8);
        dim3 g1((NOUT + 31) / 32, IN_DIM / 32);
        cast_transpose_f16<<<g1, blk>>>(w_slow, p_ws, IN_DIM, NOUT, 1);
        dim3 g2(IN_DIM / 32, IN_DIM / 32);
        cast_transpose_f16<<<g2, blk>>>(w_out, p_wo, IN_DIM, IN_DIM, 0);
    }

    // 1. LayerNorm -> f16
    ln_kernel<<<NROWS, 256>>>(x, ln_w, ln_b, p_h);

    // 2. qkvb(f16, padded) = h @ w_slow
    {
        dim3 grid(NOUT_PAD / 128, NROWS / 128);
        gemm_f16<true><<<grid, 256, GEMM_SMEM_BYTES>>>(p_h, p_ws, nullptr, p_qkvb,
                                                       NOUT2, IN_DIM);
    }

    // 3. transform
    transform_kernel<<<(NROWS * NH) / 8, 256>>>(p_qkvb, p_q, p_k, p_v, p_beta);

    // 4. delta-rule scan (2 warps/block, conflict-free, 2-step blocked)
    scan_kernel<<<BSZ * NH * 8, 64>>>(p_q, p_k, p_v, p_beta, p_o);

    // 5. out = x + scan_out @ w_out
    {
        dim3 grid(IN_DIM / 128, NROWS / 128);
        gemm_f16<false><<<grid, 256, GEMM_SMEM_BYTES>>>(p_o, p_wo, x, out,
                                                        IN_DIM, IN_DIM);
    }
}

// round 16
// speedup vs baseline: 1.2262x; 1.2262x over previous
#include <cuda_runtime.h>
#include <cuda_fp16.h>
#include <cstdint>

// Problem constants
#define SLEN   2048
#define BSZ    8
#define IN_DIM 1024
#define NH     16
#define DH     64
#define NROWS  (SLEN*BSZ)              // 16384
#define NOUT   (NH*(3*DH+1))           // 3088
#define HPAD   194                     // padded head stride
#define NOUT2  (NH*HPAD)               // 3104
#define NOUT_PAD 3200

// ---------------- device scratch ----------------
__device__ __half g_h[(size_t)NROWS * IN_DIM];
__device__ __half g_qkvb[(size_t)NROWS * NOUT2];
__device__ __half g_q[(size_t)BSZ*NH*SLEN*DH];       // f16 q/k/v
__device__ __half g_k[(size_t)BSZ*NH*SLEN*DH];
__device__ __half g_v[(size_t)BSZ*NH*SLEN*DH];
__device__ float g_beta[(size_t)BSZ*NH*SLEN];
__device__ __half g_o[(size_t)NROWS * IN_DIM];
__device__ __half g_ws_t[(size_t)NOUT_PAD * IN_DIM];
__device__ __half g_wo_t[(size_t)IN_DIM * IN_DIM];

// ---------------- helpers ----------------
__device__ __forceinline__ void cp_async16(void* smem_dst, const void* gsrc) {
    unsigned s = (unsigned)__cvta_generic_to_shared(smem_dst);
    asm volatile("cp.async.cg.shared.global [%0], [%1], 16;\n" :: "r"(s), "l"(gsrc));
}
__device__ __forceinline__ float elu_p1(float x) {
    return x > 0.f ? x + 1.f : __expf(x);
}
__device__ __forceinline__ void mma_f16(float* d, const uint32_t* a, const uint32_t* b) {
    asm volatile("mma.sync.aligned.m16n8k16.row.col.f32.f16.f16.f32 "
        "{%0,%1,%2,%3}, {%4,%5,%6,%7}, {%8,%9}, {%0,%1,%2,%3};"
        : "+f"(d[0]), "+f"(d[1]), "+f"(d[2]), "+f"(d[3])
        : "r"(a[0]), "r"(a[1]), "r"(a[2]), "r"(a[3]), "r"(b[0]), "r"(b[1]));
}
__device__ __forceinline__ void ldsm_x4(uint32_t* r, uint32_t saddr) {
    asm volatile("ldmatrix.sync.aligned.m8n8.x4.shared.b16 {%0,%1,%2,%3}, [%4];"
        : "=r"(r[0]), "=r"(r[1]), "=r"(r[2]), "=r"(r[3]) : "r"(saddr));
}
__device__ __forceinline__ void ldsm_x2(uint32_t* r, uint32_t saddr) {
    asm volatile("ldmatrix.sync.aligned.m8n8.x2.shared.b16 {%0,%1}, [%2];"
        : "=r"(r[0]), "=r"(r[1]) : "r"(saddr));
}
// load 16 contiguous halves from smem into 16 floats (2x LDS.128)
__device__ __forceinline__ void ld16h(const __half* s, float* out) {
    uint4 u0 = *(const uint4*)s;
    uint4 u1 = *(const uint4*)(s + 8);
    const uint32_t w[8] = {u0.x, u0.y, u0.z, u0.w, u1.x, u1.y, u1.z, u1.w};
    #pragma unroll
    for (int i = 0; i < 8; i++) {
        float2 f = __half22float2(*(const __half2*)&w[i]);
        out[2*i] = f.x; out[2*i+1] = f.y;
    }
}

// ---------------- cast+transpose weights: W[K][N] f32 -> T[n'][K] f16 ----------------
__global__ __launch_bounds__(256) void cast_transpose_f16(
    const float* __restrict__ W, __half* __restrict__ T, int K, int N, int pad)
{
    __shared__ float tile[32][33];
    int n0 = blockIdx.x * 32, k0 = blockIdx.y * 32;
    int tx = threadIdx.x, ty = threadIdx.y;
    #pragma unroll
    for (int i = 0; i < 32; i += 8) {
        int k = k0 + ty + i, n = n0 + tx;
        tile[ty + i][tx] = (n < N) ? W[(size_t)k * N + n] : 0.f;
    }
    __syncthreads();
    #pragma unroll
    for (int i = 0; i < 32; i += 8) {
        int n = n0 + ty + i, k = k0 + tx;
        if (n < N) {
            int np = pad ? (n + n / 193) : n;
            T[(size_t)np * K + k] = __float2half(tile[tx][ty + i]);
        }
    }
}

// ---------------- LayerNorm ----------------
__global__ __launch_bounds__(256) void ln_kernel(
    const float* __restrict__ x, const float* __restrict__ w,
    const float* __restrict__ b, __half* __restrict__ hout)
{
    int row = blockIdx.x;
    int t = threadIdx.x;
    const float4* xr = (const float4*)(x + (size_t)row * IN_DIM);
    float4 v = xr[t];
    float s  = v.x + v.y + v.z + v.w;
    float ss = v.x*v.x + v.y*v.y + v.z*v.z + v.w*v.w;
    #pragma unroll
    for (int o = 16; o; o >>= 1) {
        s  += __shfl_xor_sync(0xffffffffu, s,  o);
        ss += __shfl_xor_sync(0xffffffffu, ss, o);
    }
    __shared__ float rs[8], rss[8];
    if ((t & 31) == 0) { rs[t >> 5] = s; rss[t >> 5] = ss; }
    __syncthreads();
    float S = 0.f, SS = 0.f;
    #pragma unroll
    for (int i = 0; i < 8; i++) { S += rs[i]; SS += rss[i]; }
    float mu = S * (1.f / IN_DIM);
    float var = SS * (1.f / IN_DIM) - mu * mu;
    float rstd = rsqrtf(var + 1e-5f);
    float4 wv = ((const float4*)w)[t];
    float4 bv = ((const float4*)b)[t];
    float o0 = (v.x - mu) * rstd * wv.x + bv.x;
    float o1 = (v.y - mu) * rstd * wv.y + bv.y;
    float o2 = (v.z - mu) * rstd * wv.z + bv.z;
    float o3 = (v.w - mu) * rstd * wv.w + bv.w;
    size_t base = (size_t)row * IN_DIM;
    ((__half2*)(hout + base))[2*t]   = __half2(__float2half(o0), __float2half(o1));
    ((__half2*)(hout + base))[2*t+1] = __half2(__float2half(o2), __float2half(o3));
}

// ---------------- f16 HGEMM (ldmatrix, 128B-row XOR-swizzle, 3-stage, KT=64) ----------------
#define KT  64
#define ARR_U32 (128 * 32)
#define STAGE_U32 (2 * ARR_U32)
#define GEMM_SMEM_BYTES (3 * STAGE_U32 * 4)

template<bool HOUT>
__global__ __launch_bounds__(256, 2) void gemm_f16(
    const __half* __restrict__ A, const __half* __restrict__ B,
    const float* __restrict__ Res, void* __restrict__ Cv,
    int N, int K)
{
    extern __shared__ __align__(16) uint32_t dsm[];

    const int tid  = threadIdx.x;
    const int warp = tid >> 5;
    const int lane = tid & 31;
    const int gid  = lane >> 2;
    const int tig  = lane & 3;
    const int wm   = warp & 1;
    const int wn   = warp >> 1;
    const int row0 = blockIdx.y * 128;
    const int col0 = blockIdx.x * 128;

    float acc[4][4][4];
    #pragma unroll
    for (int i = 0; i < 4; i++)
        #pragma unroll
        for (int j = 0; j < 4; j++)
            #pragma unroll
            for (int k = 0; k < 4; k++) acc[i][j][k] = 0.f;

    const int nk = K / KT;
    const uint32_t smem0 = (uint32_t)__cvta_generic_to_shared(dsm);

    auto load_stage = [&](int kt) {
        const int k0 = kt * KT;
        uint32_t* sb = dsm + (kt % 3) * STAGE_U32;
        #pragma unroll
        for (int it = 0; it < 4; it++) {
            int c = tid + it * 256;
            int r = c >> 3, f = c & 7;
            int fs = f ^ (r & 7);
            uint32_t* dst = sb + r * 32 + fs * 4;
            cp_async16(dst,           A + (size_t)(row0 + r) * K + k0 + f * 8);
            cp_async16(dst + ARR_U32, B + (size_t)(col0 + r) * K + k0 + f * 8);
        }
        asm volatile("cp.async.commit_group;\n" ::);
    };

    load_stage(0);
    load_stage(1);

    const int a_sub = lane >> 3;
    const int a_rin = lane & 7;
    const int a_row0 = wm * 64 + (a_sub & 1) * 8 + a_rin;
    const uint32_t a_byte0 = (uint32_t)(a_row0 * 128);
    uint32_t a_ch[4];
    #pragma unroll
    for (int kb = 0; kb < 4; kb++)
        a_ch[kb] = (uint32_t)((((kb * 2) + (a_sub >> 1)) ^ a_rin) * 16);
    const int b_row0 = wn * 32 + (lane & 7);
    const int b_sub = (lane >> 3) & 1;
    const uint32_t b_byte0 = (uint32_t)(b_row0 * 128);
    uint32_t b_ch[4];
    #pragma unroll
    for (int kb = 0; kb < 4; kb++)
        b_ch[kb] = (uint32_t)((((kb * 2) + b_sub) ^ (lane & 7)) * 16);

    for (int kt = 0; kt < nk; kt++) {
        asm volatile("cp.async.wait_group 1;\n" ::);
        __syncthreads();
        if (kt + 2 < nk) load_stage(kt + 2);
        else asm volatile("cp.async.commit_group;\n" ::);

        const uint32_t sbase = smem0 + (uint32_t)((kt % 3) * STAGE_U32 * 4);
        const uint32_t sA = sbase;
        const uint32_t sB = sbase + ARR_U32 * 4;

        #pragma unroll
        for (int kb = 0; kb < 4; kb++) {
            uint32_t af[4][4];
            #pragma unroll
            for (int mt = 0; mt < 4; mt++)
                ldsm_x4(af[mt], sA + a_byte0 + (uint32_t)(mt * 16 * 128) + a_ch[kb]);
            uint32_t bf[4][2];
            #pragma unroll
            for (int nt = 0; nt < 4; nt++)
                ldsm_x2(bf[nt], sB + b_byte0 + (uint32_t)(nt * 8 * 128) + b_ch[kb]);
            #pragma unroll
            for (int nt = 0; nt < 4; nt++)
                #pragma unroll
                for (int mt = 0; mt < 4; mt++) mma_f16(acc[mt][nt], af[mt], bf[nt]);
        }
    }

    #pragma unroll
    for (int mt = 0; mt < 4; mt++) {
        #pragma unroll
        for (int nt = 0; nt < 4; nt++) {
            int r = row0 + wm * 64 + mt * 16 + gid;
            int c = col0 + wn * 32 + nt * 8 + 2 * tig;
            if (c < N) {
                size_t o0 = (size_t)r * N + c;
                size_t o1 = (size_t)(r + 8) * N + c;
                if (HOUT) {
                    __half* C = (__half*)Cv;
                    *(__half2*)&C[o0] = __half2(__float2half(acc[mt][nt][0]),
                                                __float2half(acc[mt][nt][1]));
                    *(__half2*)&C[o1] = __half2(__float2half(acc[mt][nt][2]),
                                                __float2half(acc[mt][nt][3]));
                } else {
                    float* C = (float*)Cv;
                    float2 v0 = make_float2(acc[mt][nt][0], acc[mt][nt][1]);
                    float2 v1 = make_float2(acc[mt][nt][2], acc[mt][nt][3]);
                    if (Res) {
                        float2 r0 = *(const float2*)&Res[o0];
                        float2 r1 = *(const float2*)&Res[o1];
                        v0.x += r0.x; v0.y += r0.y;
                        v1.x += r1.x; v1.y += r1.y;
                    }
                    *(float2*)&C[o0] = v0;
                    *(float2*)&C[o1] = v1;
                }
            }
        }
    }
}

// ---------------- transform: f16 qkvb -> f16 q,k,v + f32 beta ----------------
__global__ __launch_bounds__(256) void transform_kernel(
    const __half* __restrict__ qkvb,
    __half* __restrict__ Q, __half* __restrict__ Kk,
    __half* __restrict__ V, float* __restrict__ Beta)
{
    int gw   = blockIdx.x * 8 + (threadIdx.x >> 5);
    int lane = threadIdx.x & 31;
    int h  = gw & 15;
    int tb = gw >> 4;
    int b  = tb & 7;
    int t  = tb >> 3;
    const __half2* src2 = (const __half2*)(qkvb + (size_t)tb * NOUT2 + h * HPAD);
    size_t dst = ((size_t)(b * NH + h) * SLEN + t) * DH;

    float2 qf = __half22float2(src2[lane]);
    float q0 = elu_p1(qf.x), q1 = elu_p1(qf.y);
    float s = q0 + q1;
    #pragma unroll
    for (int o = 16; o; o >>= 1) s += __shfl_xor_sync(0xffffffffu, s, o);
    float inv = 1.f / s;
    ((__half2*)(Q + dst))[lane] = __half2(__float2half(q0 * inv), __float2half(q1 * inv));

    float2 kf = __half22float2(src2[32 + lane]);
    float k0 = elu_p1(kf.x), k1 = elu_p1(kf.y);
    s = k0 + k1;
    #pragma unroll
    for (int o = 16; o; o >>= 1) s += __shfl_xor_sync(0xffffffffu, s, o);
    inv = 1.f / s;
    ((__half2*)(Kk + dst))[lane] = __half2(__float2half(k0 * inv), __float2half(k1 * inv));

    ((__half2*)(V + dst))[lane] = src2[64 + lane];

    if (lane == 0) {
        float x = __half2float(((const __half*)src2)[192]);
        Beta[(size_t)(b * NH + h) * SLEN + t] = 1.f / (1.f + __expf(-x));
    }
}

// ---------------- delta-rule scan v6: r14 topology + f16 inputs ----------------
// 1024 blocks x 32 threads. lane: rloc=lane>>2 (8 rows), g=lane&3 (16 cols), W[16] f32.
// f16 smem rows = 128B; lane g reads 32B at byte g*32 (+16): banks naturally distinct.
#define CH 16
__global__ __launch_bounds__(32) void scan_kernel(
    const __half* __restrict__ Q, const __half* __restrict__ Kk,
    const __half* __restrict__ V, const float* __restrict__ Beta,
    __half* __restrict__ O)
{
    __shared__ __align__(16) __half sk[2][CH][64];
    __shared__ __align__(16) __half sq[2][CH][64];
    __shared__ __align__(16) __half sv[2][CH][8];
    __shared__ __align__(16) float  sb[2][CH];

    const int bh = blockIdx.x >> 3;
    const int w  = blockIdx.x & 7;
    const int b = bh >> 4, h = bh & 15;
    const __half* Kp = Kk + (size_t)bh * SLEN * DH;
    const __half* Vp = V  + (size_t)bh * SLEN * DH;
    const __half* Qp = Q  + (size_t)bh * SLEN * DH;
    const float*  Bp = Beta + (size_t)bh * SLEN;
    const int lane = threadIdx.x;
    const int rloc = lane >> 2;
    const int g = lane & 3;

    float W[16];
    #pragma unroll
    for (int m = 0; m < 16; m++) W[m] = 0.f;

    auto issue = [&](int c) {
        int buf = c & 1;
        int t0 = c * CH;
        // k,q: 16 steps x 128B = 128 cp16 each
        #pragma unroll
        for (int j = 0; j < 4; j++) {
            int idx = lane + j * 32;           // 0..127
            int tt = idx >> 3, f = idx & 7;
            cp_async16(&sk[buf][tt][f * 8], Kp + (size_t)(t0 + tt) * DH + f * 8);
            cp_async16(&sq[buf][tt][f * 8], Qp + (size_t)(t0 + tt) * DH + f * 8);
        }
        // v: 16 steps x 16B = 16 cp16
        if (lane < 16)
            cp_async16(&sv[buf][lane][0], Vp + (size_t)(t0 + lane) * DH + w * 8);
        // beta: 16 f32 = 4 cp16
        if (lane >= 28) cp_async16(&sb[buf][(lane - 28) * 4], Bp + t0 + (lane - 28) * 4);
        asm volatile("cp.async.commit_group;\n" ::);
    };

    issue(0); issue(1);

    const int NC = SLEN / CH;
    const size_t obase = (size_t)b * IN_DIM + h * DH + w * 8 + rloc;

    for (int c = 0; c < NC; c++) {
        asm volatile("cp.async.wait_group 1;\n" ::);
        __syncwarp();
        const int buf = c & 1;

        #pragma unroll 2
        for (int p = 0; p < CH / 2; p++) {
            const int t1 = 2 * p, t2 = 2 * p + 1;
            float k1[16], k2[16], q1v[16], q2v[16];
            ld16h(&sk[buf][t1][g * 16], k1);
            ld16h(&sk[buf][t2][g * 16], k2);
            ld16h(&sq[buf][t1][g * 16], q1v);
            ld16h(&sq[buf][t2][g * 16], q2v);
            float v1 = __half2float(sv[buf][t1][rloc]);
            float v2 = __half2float(sv[buf][t2][rloc]);
            float b1 = sb[buf][t1];
            float b2 = sb[buf][t2];

            float pk1a = 0.f, pk1b = 0.f, pk2a = 0.f, pk2b = 0.f, kka = 0.f, kkb = 0.f;
            #pragma unroll
            for (int m = 0; m < 8; m++) {
                pk1a = fmaf(W[m],     k1[m],     pk1a);
                pk1b = fmaf(W[m + 8], k1[m + 8], pk1b);
                pk2a = fmaf(W[m],     k2[m],     pk2a);
                pk2b = fmaf(W[m + 8], k2[m + 8], pk2b);
                kka  = fmaf(k1[m],     k2[m],     kka);
                kkb  = fmaf(k1[m + 8], k2[m + 8], kkb);
            }
            float pk1 = pk1a + pk1b;
            float pk2 = pk2a + pk2b;
            float kk  = kka + kkb;
            pk1 += __shfl_xor_sync(0xffffffffu, pk1, 1);
            pk2 += __shfl_xor_sync(0xffffffffu, pk2, 1);
            kk  += __shfl_xor_sync(0xffffffffu, kk,  1);
            pk1 += __shfl_xor_sync(0xffffffffu, pk1, 2);
            pk2 += __shfl_xor_sync(0xffffffffu, pk2, 2);
            kk  += __shfl_xor_sync(0xffffffffu, kk,  2);

            float d1 = b1 * (v1 - pk1);
            float d2 = b2 * (v2 - pk2 - d1 * kk);

            float po1a = 0.f, po1b = 0.f;
            #pragma unroll
            for (int m = 0; m < 8; m++) {
                W[m]     = fmaf(d1, k1[m],     W[m]);
                po1a     = fmaf(W[m],  q1v[m], po1a);
                W[m + 8] = fmaf(d1, k1[m + 8], W[m + 8]);
                po1b     = fmaf(W[m + 8], q1v[m + 8], po1b);
            }
            float po2a = 0.f, po2b = 0.f;
            #pragma unroll
            for (int m = 0; m < 8; m++) {
                W[m]     = fmaf(d2, k2[m],     W[m]);
                po2a     = fmaf(W[m],  q2v[m], po2a);
                W[m + 8] = fmaf(d2, k2[m + 8], W[m + 8]);
                po2b     = fmaf(W[m + 8], q2v[m + 8], po2b);
            }

            float po1 = po1a + po1b;
            float po2 = po2a + po2b;
            po1 += __shfl_xor_sync(0xffffffffu, po1, 1);
            po2 += __shfl_xor_sync(0xffffffffu, po2, 1);
            po1 += __shfl_xor_sync(0xffffffffu, po1, 2);
            po2 += __shfl_xor_sync(0xffffffffu, po2, 2);

            if (g == 0) {
                int tg1 = c * CH + t1;
                size_t off1 = (size_t)tg1 * (BSZ * IN_DIM) + obase;
                O[off1] = __float2half(po1);
                O[off1 + (BSZ * IN_DIM)] = __float2half(po2);
            }
        }
        __syncwarp();
        if (c + 2 < NC) issue(c + 2);
        else asm volatile("cp.async.commit_group;\n" ::);
    }
}

// ---------------- launcher ----------------
extern "C" void kernel_launch(void* const* d_in, const int* in_sizes, int n_in,
                              void* d_out, int out_size)
{
    const float* x      = (const float*)d_in[0];
    const float* ln_w   = (const float*)d_in[1];
    const float* ln_b   = (const float*)d_in[2];
    const float* w_slow = (const float*)d_in[3];
    const float* w_out  = (const float*)d_in[4];
    float* out = (float*)d_out;

    float *p_beta;
    __half *p_h, *p_qkvb, *p_q, *p_k, *p_v, *p_o, *p_ws, *p_wo;
    cudaGetSymbolAddress((void**)&p_qkvb, g_qkvb);
    cudaGetSymbolAddress((void**)&p_q,    g_q);
    cudaGetSymbolAddress((void**)&p_k,    g_k);
    cudaGetSymbolAddress((void**)&p_v,    g_v);
    cudaGetSymbolAddress((void**)&p_beta, g_beta);
    cudaGetSymbolAddress((void**)&p_h,    g_h);
    cudaGetSymbolAddress((void**)&p_o,    g_o);
    cudaGetSymbolAddress((void**)&p_ws,   g_ws_t);
    cudaGetSymbolAddress((void**)&p_wo,   g_wo_t);

    cudaFuncSetAttribute(gemm_f16<true>, cudaFuncAttributeMaxDynamicSharedMemorySize,
                         GEMM_SMEM_BYTES);
    cudaFuncSetAttribute(gemm_f16<false>, cudaFuncAttributeMaxDynamicSharedMemorySize,
                         GEMM_SMEM_BYTES);

    // 0. cast+transpose weights
    {
        dim3 blk(32, 8);
        dim3 g1((NOUT + 31) / 32, IN_DIM / 32);
        cast_transpose_f16<<<g1, blk>>>(w_slow, p_ws, IN_DIM, NOUT, 1);
        dim3 g2(IN_DIM / 32, IN_DIM / 32);
        cast_transpose_f16<<<g2, blk>>>(w_out, p_wo, IN_DIM, IN_DIM, 0);
    }

    // 1. LayerNorm -> f16
    ln_kernel<<<NROWS, 256>>>(x, ln_w, ln_b, p_h);

    // 2. qkvb(f16, padded) = h @ w_slow
    {
        dim3 grid(NOUT_PAD / 128, NROWS / 128);
        gemm_f16<true><<<grid, 256, GEMM_SMEM_BYTES>>>(p_h, p_ws, nullptr, p_qkvb,
                                                       NOUT2, IN_DIM);
    }

    // 3. transform -> f16 q/k/v
    transform_kernel<<<(NROWS * NH) / 8, 256>>>(p_qkvb, p_q, p_k, p_v, p_beta);

    // 4. delta-rule scan (1 warp/block, f16 inputs, 2-step blocked)
    scan_kernel<<<BSZ * NH * 8, 32>>>(p_q, p_k, p_v, p_beta, p_o);

    // 5. out = x + scan_out @ w_out
    {
        dim3 grid(IN_DIM / 128, NROWS / 128);
        gemm_f16<false><<<grid, 256, GEMM_SMEM_BYTES>>>(p_o, p_wo, x, out,
                                                        IN_DIM, IN_DIM);
    }
}